// round 2
// baseline (speedup 1.0000x reference)
#include <cuda_runtime.h>

#define NN 100000

// ---- scratch (static __device__ globals; no allocation) ----
__device__ int    g_deg[NN];
__device__ float  g_dinv[NN];
__device__ float4 g_sx[NN];        // dinv[v]*x[v] (xyz), w = dinv[v]
__device__ float4 g_S[NN];         // layer-1 scatter accumulator (xyz used)
__device__ float4 g_sh[NN * 4];    // [N][16] = dinv[v]*relu(h1[v]) as 4x float4
__device__ float  g_sum16[16];     // final 16-dim reduction (layer2 agg sum)

// ---------------------------------------------------------------------------
__global__ void k_init() {
    int v = blockIdx.x * blockDim.x + threadIdx.x;
    if (v < NN) {
        g_deg[v] = 1;                       // self-loop
        g_S[v]   = make_float4(0.f, 0.f, 0.f, 0.f);
    }
    if (blockIdx.x == 0 && threadIdx.x < 16) g_sum16[threadIdx.x] = 0.f;
}

// degree histogram over dst
__global__ void k_hist(const int* __restrict__ dst, int E) {
    int i      = blockIdx.x * blockDim.x + threadIdx.x;
    int stride = gridDim.x * blockDim.x;
    for (int e = i; e < E; e += stride) {
        atomicAdd(&g_deg[dst[e]], 1);
    }
}

// per-node: dinv = rsqrt(deg); sx = dinv * x
__global__ void k_node_prep(const float* __restrict__ x) {
    int v = blockIdx.x * blockDim.x + threadIdx.x;
    if (v >= NN) return;
    float d = rsqrtf((float)g_deg[v]);
    g_dinv[v] = d;
    g_sx[v] = make_float4(d * x[3 * v + 0], d * x[3 * v + 1], d * x[3 * v + 2], d);
}

// layer-1 edge scatter: S[dst] += sx[src]  (one v4 reduction per edge)
__global__ void k_scatter1(const int* __restrict__ src,
                           const int* __restrict__ dst, int E) {
    int i      = blockIdx.x * blockDim.x + threadIdx.x;
    int stride = gridDim.x * blockDim.x;
    for (int e = i; e < E; e += stride) {
        int s = src[e];
        int d = dst[e];
        float4 v = g_sx[s];
        float4* p = &g_S[d];
        asm volatile("red.global.add.v4.f32 [%0], {%1,%2,%3,%4};"
                     :: "l"(p), "f"(v.x), "f"(v.y), "f"(v.z), "f"(v.w)
                     : "memory");
    }
}

// block-wide reduce of 16 per-thread floats into g_sum16 (256 threads fixed)
__device__ __forceinline__ void block_reduce_add16(float* acc) {
    #pragma unroll
    for (int j = 0; j < 16; j++) {
        #pragma unroll
        for (int o = 16; o > 0; o >>= 1)
            acc[j] += __shfl_down_sync(0xffffffffu, acc[j], o);
    }
    __shared__ float sm[8][16];
    int lane = threadIdx.x & 31, w = threadIdx.x >> 5;
    if (lane == 0) {
        #pragma unroll
        for (int j = 0; j < 16; j++) sm[w][j] = acc[j];
    }
    __syncthreads();
    if (threadIdx.x < 16) {
        float s = 0.f;
        #pragma unroll
        for (int ww = 0; ww < 8; ww++) s += sm[ww][threadIdx.x];
        atomicAdd(&g_sum16[threadIdx.x], s);
    }
}

// layer-1 per-node: h1 = relu((dinv*(S+sx)) @ W1 + b1); sh = dinv*h1;
// also accumulates layer-2 self-loop term  sum16 += dinv*sh
__global__ void k_layer1(const float* __restrict__ W1, const float* __restrict__ b1) {
    int v = blockIdx.x * blockDim.x + threadIdx.x;
    float acc[16];
    #pragma unroll
    for (int j = 0; j < 16; j++) acc[j] = 0.f;

    if (v < NN) {
        float4 S  = g_S[v];
        float4 sx = g_sx[v];
        float  d  = sx.w;
        float a0 = d * (S.x + sx.x);
        float a1 = d * (S.y + sx.y);
        float a2 = d * (S.z + sx.z);
        float4 out[4];
        #pragma unroll
        for (int j = 0; j < 16; j++) {
            float h = __ldg(&b1[j])
                    + a0 * __ldg(&W1[j])
                    + a1 * __ldg(&W1[16 + j])
                    + a2 * __ldg(&W1[32 + j]);
            h = fmaxf(h, 0.f);
            float shv = d * h;
            ((float*)out)[j] = shv;
            acc[j] = d * shv;        // self-loop contribution to layer2 sum
        }
        g_sh[4 * v + 0] = out[0];
        g_sh[4 * v + 1] = out[1];
        g_sh[4 * v + 2] = out[2];
        g_sh[4 * v + 3] = out[3];
    }
    block_reduce_add16(acc);
}

// layer-2 edge reduction: sum16 += dinv[dst] * sh[src]  (no scatter!)
__global__ void k_edge2(const int* __restrict__ src,
                        const int* __restrict__ dst, int E) {
    float acc[16];
    #pragma unroll
    for (int j = 0; j < 16; j++) acc[j] = 0.f;

    int i      = blockIdx.x * blockDim.x + threadIdx.x;
    int stride = gridDim.x * blockDim.x;
    for (int e = i; e < E; e += stride) {
        int s = src[e];
        int d = dst[e];
        float wd = g_dinv[d];
        float4 a = g_sh[4 * s + 0];
        float4 b = g_sh[4 * s + 1];
        float4 c = g_sh[4 * s + 2];
        float4 f = g_sh[4 * s + 3];
        acc[0]  += wd * a.x;  acc[1]  += wd * a.y;  acc[2]  += wd * a.z;  acc[3]  += wd * a.w;
        acc[4]  += wd * b.x;  acc[5]  += wd * b.y;  acc[6]  += wd * b.z;  acc[7]  += wd * b.w;
        acc[8]  += wd * c.x;  acc[9]  += wd * c.y;  acc[10] += wd * c.z;  acc[11] += wd * c.w;
        acc[12] += wd * f.x;  acc[13] += wd * f.y;  acc[14] += wd * f.z;  acc[15] += wd * f.w;
    }
    block_reduce_add16(acc);
}

// final: out[j] = (sum16/N) @ W2 + b2
__global__ void k_final(const float* __restrict__ W2, const float* __restrict__ b2,
                        float* __restrict__ out) {
    int j = threadIdx.x;
    if (j >= 32) return;
    float s = __ldg(&b2[j]);
    const float inv_n = 1.0f / (float)NN;
    #pragma unroll
    for (int k = 0; k < 16; k++)
        s += (g_sum16[k] * inv_n) * __ldg(&W2[k * 32 + j]);
    out[j] = s;
}

// ---------------------------------------------------------------------------
extern "C" void kernel_launch(void* const* d_in, const int* in_sizes, int n_in,
                              void* d_out, int out_size) {
    const float* x   = (const float*)d_in[0];
    const int*   ei  = (const int*)d_in[1];
    const float* W1  = (const float*)d_in[2];
    const float* b1  = (const float*)d_in[3];
    const float* W2  = (const float*)d_in[4];
    const float* b2  = (const float*)d_in[5];
    float*       out = (float*)d_out;

    int E = in_sizes[1] / 2;
    const int* src = ei;
    const int* dst = ei + E;

    int nb_nodes = (NN + 255) / 256;
    int nb_edges = (E + 255) / 256;
    if (nb_edges > 9600) nb_edges = 9600;   // grid-stride

    k_init<<<nb_nodes, 256>>>();
    k_hist<<<nb_edges, 256>>>(dst, E);
    k_node_prep<<<nb_nodes, 256>>>(x);
    k_scatter1<<<nb_edges, 256>>>(src, dst, E);
    k_layer1<<<nb_nodes, 256>>>(W1, b1);
    k_edge2<<<1184, 256>>>(src, dst, E);    // ~8 edges/thread, register acc
    k_final<<<1, 32>>>(W2, b2, out);
}

// round 3
// speedup vs baseline: 1.3571x; 1.3571x over previous
#include <cuda_runtime.h>

#define NN 100000

// ---- scratch (static __device__ globals; no allocation) ----
__device__ int    g_deg[NN];
__device__ float  g_dinv[NN];
__device__ float4 g_sx[NN];        // dinv[v]*x[v] (xyz), w = dinv[v]
__device__ float4 g_S[NN];         // layer-1 scatter accumulator (xyz used)
__device__ float  g_w[NN];         // layer-2 src weights: dinv[v] + sum_{e:src=v} dinv[dst]
__device__ float  g_sum16[16];     // final 16-dim reduction (layer2 agg sum)

// ---------------------------------------------------------------------------
__global__ void k_init() {
    int v = blockIdx.x * blockDim.x + threadIdx.x;
    if (v < NN) {
        g_deg[v] = 1;                       // self-loop
        g_S[v]   = make_float4(0.f, 0.f, 0.f, 0.f);
    }
    if (blockIdx.x == 0 && threadIdx.x < 16) g_sum16[threadIdx.x] = 0.f;
}

// degree histogram over dst
__global__ void k_hist(const int* __restrict__ dst, int E) {
    int i      = blockIdx.x * blockDim.x + threadIdx.x;
    int stride = gridDim.x * blockDim.x;
    for (int e = i; e < E; e += stride) {
        atomicAdd(&g_deg[dst[e]], 1);
    }
}

// per-node: dinv = rsqrt(deg); sx = dinv * x; w starts at self-loop dinv
__global__ void k_node_prep(const float* __restrict__ x) {
    int v = blockIdx.x * blockDim.x + threadIdx.x;
    if (v >= NN) return;
    float d = rsqrtf((float)g_deg[v]);
    g_dinv[v] = d;
    g_w[v]    = d;   // self-loop contribution to layer-2 weight
    g_sx[v] = make_float4(d * x[3 * v + 0], d * x[3 * v + 1], d * x[3 * v + 2], d);
}

// fused edge pass:
//   layer-1:  S[dst] += sx[src]        (v4 red)
//   layer-2:  w[src] += dinv[dst]      (scalar red)
__global__ void k_scatter(const int* __restrict__ src,
                          const int* __restrict__ dst, int E) {
    int i      = blockIdx.x * blockDim.x + threadIdx.x;
    int stride = gridDim.x * blockDim.x;
    for (int e = i; e < E; e += stride) {
        int s = src[e];
        int d = dst[e];
        float4 v  = g_sx[s];
        float  dd = g_dinv[d];
        float4* p = &g_S[d];
        asm volatile("red.global.add.v4.f32 [%0], {%1,%2,%3,%4};"
                     :: "l"(p), "f"(v.x), "f"(v.y), "f"(v.z), "f"(v.w)
                     : "memory");
        asm volatile("red.global.add.f32 [%0], %1;"
                     :: "l"(&g_w[s]), "f"(dd)
                     : "memory");
    }
}

// block-wide reduce of 16 per-thread floats into g_sum16 (256 threads fixed)
__device__ __forceinline__ void block_reduce_add16(float* acc) {
    #pragma unroll
    for (int j = 0; j < 16; j++) {
        #pragma unroll
        for (int o = 16; o > 0; o >>= 1)
            acc[j] += __shfl_down_sync(0xffffffffu, acc[j], o);
    }
    __shared__ float sm[8][16];
    int lane = threadIdx.x & 31, w = threadIdx.x >> 5;
    if (lane == 0) {
        #pragma unroll
        for (int j = 0; j < 16; j++) sm[w][j] = acc[j];
    }
    __syncthreads();
    if (threadIdx.x < 16) {
        float s = 0.f;
        #pragma unroll
        for (int ww = 0; ww < 8; ww++) s += sm[ww][threadIdx.x];
        atomicAdd(&g_sum16[threadIdx.x], s);
    }
}

// layer-1 per-node + layer-2 accumulation:
//   h1 = relu((dinv*(S+sx)) @ W1 + b1)
//   sum16 += w[v] * dinv[v] * h1[v]        (covers all layer-2 terms incl. self-loop)
__global__ void k_layer1(const float* __restrict__ W1, const float* __restrict__ b1) {
    int v = blockIdx.x * blockDim.x + threadIdx.x;
    float acc[16];
    #pragma unroll
    for (int j = 0; j < 16; j++) acc[j] = 0.f;

    if (v < NN) {
        float4 S  = g_S[v];
        float4 sx = g_sx[v];
        float  d  = sx.w;
        float  wv = g_w[v] * d;   // w[v] * dinv[v]
        float a0 = d * (S.x + sx.x);
        float a1 = d * (S.y + sx.y);
        float a2 = d * (S.z + sx.z);
        #pragma unroll
        for (int j = 0; j < 16; j++) {
            float h = __ldg(&b1[j])
                    + a0 * __ldg(&W1[j])
                    + a1 * __ldg(&W1[16 + j])
                    + a2 * __ldg(&W1[32 + j]);
            h = fmaxf(h, 0.f);
            acc[j] = wv * h;
        }
    }
    block_reduce_add16(acc);
}

// final: out[j] = (sum16/N) @ W2 + b2
__global__ void k_final(const float* __restrict__ W2, const float* __restrict__ b2,
                        float* __restrict__ out) {
    int j = threadIdx.x;
    if (j >= 32) return;
    float s = __ldg(&b2[j]);
    const float inv_n = 1.0f / (float)NN;
    #pragma unroll
    for (int k = 0; k < 16; k++)
        s += (g_sum16[k] * inv_n) * __ldg(&W2[k * 32 + j]);
    out[j] = s;
}

// ---------------------------------------------------------------------------
extern "C" void kernel_launch(void* const* d_in, const int* in_sizes, int n_in,
                              void* d_out, int out_size) {
    const float* x   = (const float*)d_in[0];
    const int*   ei  = (const int*)d_in[1];
    const float* W1  = (const float*)d_in[2];
    const float* b1  = (const float*)d_in[3];
    const float* W2  = (const float*)d_in[4];
    const float* b2  = (const float*)d_in[5];
    float*       out = (float*)d_out;

    int E = in_sizes[1] / 2;
    const int* src = ei;
    const int* dst = ei + E;

    int nb_nodes = (NN + 255) / 256;
    int nb_edges = (E + 255) / 256;
    if (nb_edges > 9600) nb_edges = 9600;   // grid-stride

    k_init<<<nb_nodes, 256>>>();
    k_hist<<<nb_edges, 256>>>(dst, E);
    k_node_prep<<<nb_nodes, 256>>>(x);
    k_scatter<<<nb_edges, 256>>>(src, dst, E);
    k_layer1<<<nb_nodes, 256>>>(W1, b1);
    k_final<<<1, 32>>>(W2, b2, out);
}